// round 2
// baseline (speedup 1.0000x reference)
#include <cuda_runtime.h>
#include <math.h>

#define NUM_L0 32
#define NUM_L1 16
#define NUM_L2 8
#define IN_W   120            // 32 + 48 + 40 floats
#define N_VD   120            // C(16,2)
#define N_TD   28             // C(8,2)
#define OUT_W  204            // 32 + 16 + 8 + 120 + 28
#define EPS_N  1e-6f
#define WARPS_PER_BLOCK 8

// input layout
#define VOFF   32             // vecs 16x3
#define TOFF   80             // tens 8x5
// output layout
#define O_VN   32
#define O_TN   48
#define O_VD   56
#define O_TD   176

// packed upper-triangle pair tables: (i<<4)|j for 16, (i<<3)|j for 8
__constant__ unsigned char VP[N_VD] = {
    // i=0, j=1..15
    1,2,3,4,5,6,7,8,9,10,11,12,13,14,15,
    // i=1, j=2..15
    18,19,20,21,22,23,24,25,26,27,28,29,30,31,
    // i=2
    35,36,37,38,39,40,41,42,43,44,45,46,47,
    // i=3
    52,53,54,55,56,57,58,59,60,61,62,63,
    // i=4
    69,70,71,72,73,74,75,76,77,78,79,
    // i=5
    86,87,88,89,90,91,92,93,94,95,
    // i=6
    103,104,105,106,107,108,109,110,111,
    // i=7
    120,121,122,123,124,125,126,127,
    // i=8
    137,138,139,140,141,142,143,
    // i=9
    154,155,156,157,158,159,
    // i=10
    171,172,173,174,175,
    // i=11
    188,189,190,191,
    // i=12
    205,206,207,
    // i=13
    222,223,
    // i=14
    239
};
__constant__ unsigned char TP[N_TD] = {
    1,2,3,4,5,6,7,
    10,11,12,13,14,15,
    19,20,21,22,23,
    28,29,30,31,
    37,38,39,
    46,47,
    55
};

__global__ __launch_bounds__(32 * WARPS_PER_BLOCK)
void invariant_extractor_kernel(const float4* __restrict__ h4,
                                float4* __restrict__ out4,
                                int n_atoms) {
    // all scratch 16B-aligned
    __shared__ float4 s_in4 [WARPS_PER_BLOCK][IN_W / 4];    // full input row (only chunks 8..29 used)
    __shared__ float4 s_out4[WARPS_PER_BLOCK][OUT_W / 4];   // assembled output row
    __shared__ float4 s_v   [WARPS_PER_BLOCK][NUM_L1];      // normalized vecs, padded to 4
    __shared__ float4 s_t   [WARPS_PER_BLOCK][NUM_L2][2];   // normalized tens, padded to 8

    const int w    = threadIdx.x >> 5;
    const int lane = threadIdx.x & 31;
    const int atom = blockIdx.x * WARPS_PER_BLOCK + w;
    if (atom >= n_atoms) return;

    float*  si = (float*)s_in4[w];
    float*  so = (float*)s_out4[w];
    float4* sv = s_v[w];
    float*  st = (float*)s_t[w];

    // ---- vectorized coalesced load: 30 float4 chunks ----
    const float4* row4 = h4 + (size_t)atom * (IN_W / 4);
    if (lane < IN_W / 4) {
        float4 v = row4[lane];
        if (lane < 8) {
            // scalar pass-through: straight into the output staging row
            s_out4[w][lane] = v;
        } else {
            s_in4[w][lane] = v;
        }
    }
    __syncwarp();

    // ---- norms + normalization into padded scratch ----
    if (lane < NUM_L1) {
        const int b = VOFF + 3 * lane;
        float x = si[b], y = si[b + 1], z = si[b + 2];
        float nrm = fmaxf(sqrtf(x * x + y * y + z * z), EPS_N);
        so[O_VN + lane] = nrm;
        float inv = 1.0f / nrm;
        sv[lane] = make_float4(x * inv, y * inv, z * inv, 0.0f);
    } else if (lane < NUM_L1 + NUM_L2) {
        const int t = lane - NUM_L1;
        const int b = TOFF + 5 * t;
        float c0 = si[b], c1 = si[b+1], c2 = si[b+2], c3 = si[b+3], c4 = si[b+4];
        float nrm = fmaxf(sqrtf(c0*c0 + c1*c1 + c2*c2 + c3*c3 + c4*c4), EPS_N);
        so[O_TN + t] = nrm;
        float inv = 1.0f / nrm;
        float4* tp = (float4*)(st + 8 * t);
        tp[0] = make_float4(c0 * inv, c1 * inv, c2 * inv, c3 * inv);
        st[8 * t + 4] = c4 * inv;
    }
    __syncwarp();

    // ---- vector pair dots: 4 per lane, table-driven indices ----
    #pragma unroll
    for (int u = 0; u < 4; u++) {
        const int p = lane + 32 * u;
        if (p < N_VD) {
            const int ij = VP[p];
            const float4 a = sv[ij >> 4];
            const float4 b = sv[ij & 15];
            float d = a.x * b.x + a.y * b.y + a.z * b.z;
            so[O_VD + p] = fminf(fmaxf(d, -1.0f), 1.0f);
        }
    }

    // ---- tensor pair dots: lanes 0..27 ----
    if (lane < N_TD) {
        const int ij = TP[lane];
        const float* a = st + 8 * (ij >> 3);
        const float* b = st + 8 * (ij & 7);
        const float4 a0 = *(const float4*)a;
        const float4 b0 = *(const float4*)b;
        float d = a0.x * b0.x + a0.y * b0.y + a0.z * b0.z + a0.w * b0.w + a[4] * b[4];
        so[O_TD + lane] = fminf(fmaxf(d, -1.0f), 1.0f);
    }
    __syncwarp();

    // ---- vectorized coalesced store: 51 float4 chunks ----
    float4* orow = out4 + (size_t)atom * (OUT_W / 4);
    orow[lane] = s_out4[w][lane];
    const int k2 = lane + 32;
    if (k2 < OUT_W / 4) orow[k2] = s_out4[w][k2];
}

extern "C" void kernel_launch(void* const* d_in, const int* in_sizes, int n_in,
                              void* d_out, int out_size) {
    const float4* h = (const float4*)d_in[0];
    float4* out = (float4*)d_out;
    const int n_atoms = in_sizes[0] / IN_W;

    const int threads = 32 * WARPS_PER_BLOCK;
    const int blocks = (n_atoms + WARPS_PER_BLOCK - 1) / WARPS_PER_BLOCK;
    invariant_extractor_kernel<<<blocks, threads>>>(h, out, n_atoms);
}

// round 3
// speedup vs baseline: 3.0821x; 3.0821x over previous
#include <cuda_runtime.h>
#include <math.h>

#define NUM_L0 32
#define NUM_L1 16
#define NUM_L2 8
#define IN_W   120            // 32 + 48 + 40 floats
#define N_VD   120            // C(16,2)
#define N_TD   28             // C(8,2)
#define OUT_W  204            // 32 + 16 + 8 + 120 + 28
#define EPS_N  1e-6f
#define WARPS_PER_BLOCK 8

// input layout
#define VOFF   32             // vecs 16x3
#define TOFF   80             // tens 8x5
// output layout
#define O_VN   32
#define O_TN   48
#define O_VD   56
#define O_TD   176

__global__ __launch_bounds__(32 * WARPS_PER_BLOCK)
void invariant_extractor_kernel(const float4* __restrict__ h4,
                                float4* __restrict__ out4,
                                int n_atoms) {
    __shared__ float4 s_in4 [WARPS_PER_BLOCK][IN_W / 4];    // raw vec/tens part of input row
    __shared__ float4 s_out4[WARPS_PER_BLOCK][OUT_W / 4];   // assembled output row
    __shared__ float4 s_v   [WARPS_PER_BLOCK][NUM_L1];      // normalized vecs, padded to 4
    __shared__ float4 s_t   [WARPS_PER_BLOCK][NUM_L2][2];   // normalized tens, padded to 8
    __shared__ unsigned char s_vp[N_VD];                    // (i<<4)|j pair table, 16 channels
    __shared__ unsigned char s_tp[N_TD];                    // (i<<3)|j pair table, 8 channels

    const int tid  = threadIdx.x;
    const int w    = tid >> 5;
    const int lane = tid & 31;
    const int atom = blockIdx.x * WARPS_PER_BLOCK + w;

    // ---- issue the row load as early as possible ----
    float4 v = make_float4(0.f, 0.f, 0.f, 0.f);
    const bool valid = (atom < n_atoms);
    if (valid && lane < IN_W / 4)
        v = h4[(size_t)atom * (IN_W / 4) + lane];

    // ---- build pair-index tables once per block (off the constant port!) ----
    if (tid < N_VD + N_TD) {
        int p, n;
        if (tid < N_VD) { p = tid; n = NUM_L1; }
        else            { p = tid - N_VD; n = NUM_L2; }
        int i = 0, rem = p;
        while (rem >= n - 1 - i) { rem -= n - 1 - i; i++; }
        int j = i + 1 + rem;
        if (tid < N_VD) s_vp[tid]        = (unsigned char)((i << 4) | j);
        else            s_tp[tid - N_VD] = (unsigned char)((i << 3) | j);
    }

    // ---- stage the loaded chunk ----
    if (valid && lane < IN_W / 4) {
        if (lane < 8) s_out4[w][lane] = v;   // scalar pass-through
        else          s_in4[w][lane]  = v;
    }
    __syncthreads();   // tables + per-warp staging visible

    if (!valid) return;

    float*  si = (float*)s_in4[w];
    float*  so = (float*)s_out4[w];
    float4* sv = s_v[w];
    float*  st = (float*)s_t[w];

    // ---- norms + normalization into padded scratch ----
    if (lane < NUM_L1) {
        const int b = VOFF + 3 * lane;
        float x = si[b], y = si[b + 1], z = si[b + 2];
        float nrm = fmaxf(sqrtf(x * x + y * y + z * z), EPS_N);
        so[O_VN + lane] = nrm;
        float inv = 1.0f / nrm;
        sv[lane] = make_float4(x * inv, y * inv, z * inv, 0.0f);
    } else if (lane < NUM_L1 + NUM_L2) {
        const int t = lane - NUM_L1;
        const int b = TOFF + 5 * t;
        float c0 = si[b], c1 = si[b+1], c2 = si[b+2], c3 = si[b+3], c4 = si[b+4];
        float nrm = fmaxf(sqrtf(c0*c0 + c1*c1 + c2*c2 + c3*c3 + c4*c4), EPS_N);
        so[O_TN + t] = nrm;
        float inv = 1.0f / nrm;
        *(float4*)(st + 8 * t) = make_float4(c0 * inv, c1 * inv, c2 * inv, c3 * inv);
        st[8 * t + 4] = c4 * inv;
    }
    __syncwarp();

    // ---- vector pair dots: 4 per lane, smem-table-driven indices ----
    #pragma unroll
    for (int u = 0; u < 4; u++) {
        const int p = lane + 32 * u;
        if (p < N_VD) {
            const int ij = s_vp[p];
            const float4 a = sv[ij >> 4];
            const float4 b = sv[ij & 15];
            float d = a.x * b.x + a.y * b.y + a.z * b.z;
            so[O_VD + p] = fminf(fmaxf(d, -1.0f), 1.0f);
        }
    }

    // ---- tensor pair dots: lanes 0..27 ----
    if (lane < N_TD) {
        const int ij = s_tp[lane];
        const float* a = st + 8 * (ij >> 3);
        const float* b = st + 8 * (ij & 7);
        const float4 a0 = *(const float4*)a;
        const float4 b0 = *(const float4*)b;
        float d = a0.x * b0.x + a0.y * b0.y + a0.z * b0.z + a0.w * b0.w + a[4] * b[4];
        so[O_TD + lane] = fminf(fmaxf(d, -1.0f), 1.0f);
    }
    __syncwarp();

    // ---- vectorized coalesced store: 51 float4 chunks ----
    float4* orow = out4 + (size_t)atom * (OUT_W / 4);
    orow[lane] = s_out4[w][lane];
    const int k2 = lane + 32;
    if (k2 < OUT_W / 4) orow[k2] = s_out4[w][k2];
}

extern "C" void kernel_launch(void* const* d_in, const int* in_sizes, int n_in,
                              void* d_out, int out_size) {
    const float4* h = (const float4*)d_in[0];
    float4* out = (float4*)d_out;
    const int n_atoms = in_sizes[0] / IN_W;

    const int threads = 32 * WARPS_PER_BLOCK;
    const int blocks = (n_atoms + WARPS_PER_BLOCK - 1) / WARPS_PER_BLOCK;
    invariant_extractor_kernel<<<blocks, threads>>>(h, out, n_atoms);
}